// round 15
// baseline (speedup 1.0000x reference)
#include <cuda_runtime.h>
#include <cuda_fp16.h>
#include <math.h>
#include <stdint.h>

#define N_NODES 150000
#define N_ETYPES 1000
#define B_EDGES 16384
#define H 128
#define P_IN 336
#define P_HID 64

// Node GEMM: z[150016, 512] = A[150016, 192] @ W[192, 512]  (fp16, f16 accum x2 chains)
// Column permutation (physical fragment col p -> logical gate/h):
//   g = (p&1) | (((p>>3)&1)<<1),  h = ((p>>1)&3) | ((p>>4)<<2)
#define KTILES 12
#define MTILE 128
#define M_TILES 1172           // ceil(150000/128); 150016 padded rows

// Edge GEMM: hid[16384, 64] = comb[16384, 352] @ W1e[352, 64]
#define EKT 22                 // 352/16

// B fragments (node W), uint4 per lane: [sl(12)][npair(32)][lane(32)] uint4
__device__ __align__(16) uint4 g_Wpack4[KTILES * 32 * 32];
// A fragments: [mt(1172)][kt(12)][sub(8)][lane(32)] uint4  (57.6 MB)
__device__ __align__(16) uint4 g_Aext[(size_t)M_TILES * 12 * 8 * 32];
// W1 fragments (edge): [kt(22)][nt(8)][lane(32)] uint2
__device__ __align__(16) uint2 g_W1pack[EKT * 8 * 32];

// ---------------------------------------------------------------------------
__device__ __forceinline__ unsigned short f2h_bits(float f) {
    return __half_as_ushort(__float2half_rn(f));
}
__device__ __forceinline__ uint32_t pack_h2(float a, float b) {
    return (uint32_t)f2h_bits(a) | ((uint32_t)f2h_bits(b) << 16);
}
// single-MUFU nonlinearities (MUFU.TANH)
__device__ __forceinline__ float tanh_mufu(float x) {
    float y;
    asm("tanh.approx.f32 %0, %1;" : "=f"(y) : "f"(x));
    return y;
}
__device__ __forceinline__ float sig_mufu(float x) {
    return fmaf(0.5f, tanh_mufu(0.5f * x), 0.5f);
}
__device__ __forceinline__ float sigf(float x) {
    return __fdividef(1.0f, 1.0f + __expf(-x));
}
// f32-accum mma (edge kernel)
__device__ __forceinline__ void mma16816(float* c, const uint4 a, uint32_t bx, uint32_t by) {
    asm volatile("mma.sync.aligned.m16n8k16.row.col.f32.f16.f16.f32 "
        "{%0,%1,%2,%3}, {%4,%5,%6,%7}, {%8,%9}, {%0,%1,%2,%3};"
        : "+f"(c[0]), "+f"(c[1]), "+f"(c[2]), "+f"(c[3])
        : "r"(a.x), "r"(a.y), "r"(a.z), "r"(a.w), "r"(bx), "r"(by));
}
// f16-accum mma (node GEMM): D/C packed half2 x2
__device__ __forceinline__ void mma16816_h(uint32_t* c, const uint4 a, uint32_t bx, uint32_t by) {
    asm volatile("mma.sync.aligned.m16n8k16.row.col.f16.f16.f16.f16 "
        "{%0,%1}, {%2,%3,%4,%5}, {%6,%7}, {%0,%1};"
        : "+r"(c[0]), "+r"(c[1])
        : "r"(a.x), "r"(a.y), "r"(a.z), "r"(a.w), "r"(bx), "r"(by));
}
__device__ __forceinline__ float2 h2f2(uint32_t u) {
    __half2 h = *reinterpret_cast<__half2*>(&u);
    return __half22float2(h);
}

// ---------------------------------------------------------------------------
// Kernel 1: pack node W and edge W1e fragments (merged).
// ---------------------------------------------------------------------------
__device__ __forceinline__ unsigned short w_bits_gh(
    int k, int g, int h, const float* Wx, const float* Wh, const float* bg)
{
    float w;
    if (k < 128)       w = Wh[(g * 128 + k) * 128 + h];
    else if (k < 178)  w = Wx[(g * 50 + (k - 128)) * 128 + h];
    else if (k == 178) w = bg[g * 128 + h];
    else               w = 0.0f;
    return f2h_bits(w);
}
__device__ __forceinline__ unsigned short w1e_bits(
    int k, int n, const float* W1, const float* b1)
{
    float w;
    if (k < P_IN)       w = W1[k * P_HID + n];
    else if (k == P_IN) w = b1[n];
    else                w = 0.0f;
    return f2h_bits(w);
}

__global__ void prep_all_kernel(const float* __restrict__ Wx,
                                const float* __restrict__ Wh,
                                const float* __restrict__ bg,
                                const float* __restrict__ W1,
                                const float* __restrict__ b1)
{
    int idx = blockIdx.x * blockDim.x + threadIdx.x;
    if (idx < KTILES * 32 * 32 * 4) {
        int r    = idx & 3;
        int lane = (idx >> 2) & 31;
        int np   = (idx >> 7) & 31;
        int sl   = idx >> 12;
        int n8   = np * 2 + (r >> 1);
        int whc  = r & 1;
        int p    = n8 * 8 + (lane >> 2);
        int g    = (p & 1) | (((p >> 3) & 1) << 1);
        int h    = ((p >> 1) & 3) | ((p >> 4) << 2);
        int k0   = sl * 16 + (lane & 3) * 2 + whc * 8;
        unsigned short u0 = w_bits_gh(k0,     g, h, Wx, Wh, bg);
        unsigned short u1 = w_bits_gh(k0 + 1, g, h, Wx, Wh, bg);
        ((uint32_t*)g_Wpack4)[idx] = (uint32_t)u0 | ((uint32_t)u1 << 16);
    }
    if (idx < EKT * 8 * 32 * 2) {
        int r    = idx & 1;
        int lane = (idx >> 1) & 31;
        int nt   = (idx >> 6) & 7;
        int kt   = idx >> 9;
        int n    = nt * 8 + (lane >> 2);
        int k0   = kt * 16 + (lane & 3) * 2 + r * 8;
        unsigned short u0 = w1e_bits(k0,     n, W1, b1);
        unsigned short u1 = w1e_bits(k0 + 1, n, W1, b1);
        ((uint32_t*)g_W1pack)[idx] = (uint32_t)u0 | ((uint32_t)u1 << 16);
    }
}

// ---------------------------------------------------------------------------
// Kernel 2: build A in mma A-fragment order (single fp16 pass). (R10 exact)
// ---------------------------------------------------------------------------
__global__ void __launch_bounds__(256) build_a_kernel(
    const float* __restrict__ node_cont,
    const int*   __restrict__ ncat_codes,
    const float* __restrict__ ncat_emb,
    const float* __restrict__ h_prev)
{
    __shared__ float xs[128][64];

    const int tid  = threadIdx.x;
    const int lane = tid & 31;
    const int w    = tid >> 5;
    const int mt   = blockIdx.x;
    const int n0m  = mt * MTILE;

    for (int it = 0; it < 32; ++it) {
        int e = tid + it * 256;
        int row = e >> 6, kr = e & 63;
        int node = n0m + row;
        float v = 0.0f;
        if (node < N_NODES) {
            if (kr < 2)        v = node_cont[node * 2 + kr];
            else if (kr < 50)  {
                int j = (kr - 2) >> 4, kd = (kr - 2) & 15;
                int code = ncat_codes[j * N_NODES + node];
                v = ncat_emb[(j * 64 + code) * 16 + kd];
            } else if (kr == 50) v = 1.0f;
        }
        xs[row][kr] = v;
    }
    __syncthreads();

    const int gr   = lane >> 2;
    const int kc   = (lane & 3) * 2;
    const int r0   = w * 16 + gr;
    const int r1   = r0 + 8;
    const int nd0  = n0m + r0;
    const int nd1  = n0m + r1;

    #pragma unroll 2
    for (int sl = 0; sl < 12; ++sl) {
        int kg = sl * 16 + kc;
        float2 s00, s01, s10, s11;
        if (kg < 128) {
            s00 = (nd0 < N_NODES) ? *(const float2*)(h_prev + (size_t)nd0 * H + kg)
                                  : make_float2(0.f, 0.f);
            s10 = (nd1 < N_NODES) ? *(const float2*)(h_prev + (size_t)nd1 * H + kg)
                                  : make_float2(0.f, 0.f);
        } else {
            s00 = *(const float2*)&xs[r0][kg - 128];
            s10 = *(const float2*)&xs[r1][kg - 128];
        }
        int kg8 = kg + 8;
        if (kg8 < 128) {
            s01 = (nd0 < N_NODES) ? *(const float2*)(h_prev + (size_t)nd0 * H + kg8)
                                  : make_float2(0.f, 0.f);
            s11 = (nd1 < N_NODES) ? *(const float2*)(h_prev + (size_t)nd1 * H + kg8)
                                  : make_float2(0.f, 0.f);
        } else {
            s01 = *(const float2*)&xs[r0][kg8 - 128];
            s11 = *(const float2*)&xs[r1][kg8 - 128];
        }
        uint4 hi4;
        hi4.x = pack_h2(s00.x, s00.y);
        hi4.y = pack_h2(s10.x, s10.y);
        hi4.z = pack_h2(s01.x, s01.y);
        hi4.w = pack_h2(s11.x, s11.y);
        g_Aext[(((size_t)mt * 12 + sl) * 8 + w) * 32 + lane] = hi4;
    }
}

// ---------------------------------------------------------------------------
// Kernel 3: GEMM (f16 accum, 2 split-K chains) + fused LSTM epilogue.
// 256 thr = 8 warps (4m x 2n), warp tile 32x32, 3 CTAs/SM.
// Chain A: kt 0-5; chain B: kt 6-11; summed in fp32 at epilogue.
// ---------------------------------------------------------------------------
__global__ void __launch_bounds__(256, 3) gemm_lstm_kernel(
    const float* __restrict__ c_prev,
    const float* __restrict__ w_c,
    float* __restrict__ h_new,
    float* __restrict__ c_new)
{
    const int tid  = threadIdx.x;
    const int lane = tid & 31;
    const int wid  = tid >> 5;
    const int wm   = wid & 3;          // 0..3
    const int wn   = wid >> 2;         // 0..1
    const int mt   = blockIdx.x >> 3;
    const int c    = blockIdx.x & 7;
    const int Cw   = c * 2 + wn;       // 32-col warp chunk 0..15

    // acch[chain][mtt][nt][2 u32]  (u32 = packed half2: {row, row} x {col0,col1})
    uint32_t acch[2][2][4][2];
    #pragma unroll
    for (int ch = 0; ch < 2; ++ch)
        #pragma unroll
        for (int mtt = 0; mtt < 2; ++mtt)
            #pragma unroll
            for (int nt = 0; nt < 4; ++nt) {
                acch[ch][mtt][nt][0] = 0u;
                acch[ch][mtt][nt][1] = 0u;
            }

    const uint4* __restrict__ abase =
        g_Aext + ((size_t)mt * 12 * 8 + wm * 2) * 32 + lane;
    const uint4* __restrict__ bbase =
        g_Wpack4 + (Cw * 2) * 32 + lane;

    #pragma unroll 2
    for (int kt = 0; kt < KTILES; ++kt) {
        const int ch = (kt < 6) ? 0 : 1;
        uint4 a0 = abase[(size_t)(kt * 8 + 0) * 32];
        uint4 a1 = abase[(size_t)(kt * 8 + 1) * 32];
        uint4 b0 = bbase[(size_t)(kt * 32 + 0) * 32];
        uint4 b1 = bbase[(size_t)(kt * 32 + 1) * 32];
        mma16816_h(acch[ch][0][0], a0, b0.x, b0.y);
        mma16816_h(acch[ch][1][0], a1, b0.x, b0.y);
        mma16816_h(acch[ch][0][1], a0, b0.z, b0.w);
        mma16816_h(acch[ch][1][1], a1, b0.z, b0.w);
        mma16816_h(acch[ch][0][2], a0, b1.x, b1.y);
        mma16816_h(acch[ch][1][2], a1, b1.x, b1.y);
        mma16816_h(acch[ch][0][3], a0, b1.z, b1.w);
        mma16816_h(acch[ch][1][3], a1, b1.z, b1.w);
    }

    // ---- fused LSTM epilogue.
    // f16 D layout: reg0 = (row gr, cols qq*2, qq*2+1), reg1 = (row gr+8, same cols).
    // nt = 2*j holds gates (g0,g1); nt = 2*j+1 holds (g2,g3) for h = (Cw*2+j)*4+qq.
    const int gr = lane >> 2, qq = lane & 3;
    #pragma unroll
    for (int j = 0; j < 2; ++j) {
        const int h = (Cw * 2 + j) * 4 + qq;
        const float wi = w_c[h];
        const float wf = w_c[128 + h];
        const float wo = w_c[256 + h];
        #pragma unroll
        for (int mtt = 0; mtt < 2; ++mtt) {
            size_t node0 = (size_t)mt * 128 + wm * 32 + mtt * 16 + gr;
            #pragma unroll
            for (int half = 0; half < 2; ++half) {
                size_t node = node0 + half * 8;
                if (node < N_NODES) {
                    float2 pA0 = h2f2(acch[0][mtt][2*j][half]);
                    float2 pB0 = h2f2(acch[1][mtt][2*j][half]);
                    float2 pA1 = h2f2(acch[0][mtt][2*j+1][half]);
                    float2 pB1 = h2f2(acch[1][mtt][2*j+1][half]);
                    float z0 = pA0.x + pB0.x;   // gate 0
                    float z1 = pA0.y + pB0.y;   // gate 1
                    float z2 = pA1.x + pB1.x;   // gate 2
                    float z3 = pA1.y + pB1.y;   // gate 3
                    size_t off = node * H + h;
                    float cv = c_prev[off];
                    float ig = sig_mufu(z0 + wi * cv);
                    float fg = sig_mufu(z1 + wf * cv);
                    float tg = tanh_mufu(z2);
                    float cn = fg * cv + ig * tg;
                    float og = sig_mufu(z3 + wo * cn);
                    c_new[off] = cn;
                    h_new[off] = og * tanh_mufu(cn);
                }
            }
        }
    }
}

// ---------------------------------------------------------------------------
// Kernel 4: Edge MLP via tensor cores (R12 logic; 128-thr blocks, grid 256).
// ---------------------------------------------------------------------------
__global__ void __launch_bounds__(128) edge_mlp_tc_kernel(
    const int*   __restrict__ src_ids, const int* __restrict__ dst_ids,
    const int*   __restrict__ etype_ids, const float* __restrict__ t_rel,
    const int*   __restrict__ ecat_codes, const float* __restrict__ eid_emb,
    const float* __restrict__ ecat_emb, const float* __restrict__ time_W,
    const float* __restrict__ time_b, const float* __restrict__ W2,
    const float* __restrict__ b2, const float* __restrict__ h_new,
    float* __restrict__ prob)
{
    const int lane = threadIdx.x & 31;
    const int w    = threadIdx.x >> 5;        // 0..3
    const int gr   = lane >> 2;
    const int qq   = lane & 3;

    const int r0 = blockIdx.x * 64 + w * 16 + gr;
    const int r1 = r0 + 8;

    const int e0 = etype_ids[r0], e1 = etype_ids[r1];
    const float t0 = t_rel[r0],   t1 = t_rel[r1];
    const float* ps0 = h_new + (size_t)src_ids[r0] * H;
    const float* ps1 = h_new + (size_t)src_ids[r1] * H;
    const float* pd0 = h_new + (size_t)dst_ids[r0] * H;
    const float* pd1 = h_new + (size_t)dst_ids[r1] * H;
    const float* pe0 = eid_emb + e0 * 32;
    const float* pe1 = eid_emb + e1 * 32;
    const float* pc00 = ecat_emb + ecat_codes[e0] * 16;
    const float* pc01 = ecat_emb + (32 + ecat_codes[N_ETYPES + e0]) * 16;
    const float* pc10 = ecat_emb + ecat_codes[e1] * 16;
    const float* pc11 = ecat_emb + (32 + ecat_codes[N_ETYPES + e1]) * 16;

    float acc[8][4];
    #pragma unroll
    for (int nt = 0; nt < 8; ++nt)
        #pragma unroll
        for (int q = 0; q < 4; ++q) acc[nt][q] = 0.0f;

    const uint2* __restrict__ bbase = g_W1pack + lane;
    const int off = qq * 2;

    #pragma unroll
    for (int kt = 0; kt < EKT; ++kt) {
        float2 v00, v01, v10, v11;
        if (kt < 8) {
            int o = kt * 16 + off;
            v00 = *(const float2*)(ps0 + o);     v01 = *(const float2*)(ps0 + o + 8);
            v10 = *(const float2*)(ps1 + o);     v11 = *(const float2*)(ps1 + o + 8);
        } else if (kt < 16) {
            int o = (kt - 8) * 16 + off;
            v00 = *(const float2*)(pd0 + o);     v01 = *(const float2*)(pd0 + o + 8);
            v10 = *(const float2*)(pd1 + o);     v11 = *(const float2*)(pd1 + o + 8);
        } else if (kt < 18) {
            int o = (kt - 16) * 16 + off;
            v00 = *(const float2*)(pe0 + o);     v01 = *(const float2*)(pe0 + o + 8);
            v10 = *(const float2*)(pe1 + o);     v11 = *(const float2*)(pe1 + o + 8);
        } else if (kt == 18) {
            v00 = *(const float2*)(pc00 + off);  v01 = *(const float2*)(pc00 + off + 8);
            v10 = *(const float2*)(pc10 + off);  v11 = *(const float2*)(pc10 + off + 8);
        } else if (kt == 19) {
            v00 = *(const float2*)(pc01 + off);  v01 = *(const float2*)(pc01 + off + 8);
            v10 = *(const float2*)(pc11 + off);  v11 = *(const float2*)(pc11 + off + 8);
        } else if (kt == 20) {
            float2 wA = *(const float2*)(time_W + off);
            float2 wB = *(const float2*)(time_W + off + 8);
            float2 bA = *(const float2*)(time_b + off);
            float2 bB = *(const float2*)(time_b + off + 8);
            v00 = make_float2(fmaf(t0, wA.x, bA.x), fmaf(t0, wA.y, bA.y));
            v01 = make_float2(fmaf(t0, wB.x, bB.x), fmaf(t0, wB.y, bB.y));
            v10 = make_float2(fmaf(t1, wA.x, bA.x), fmaf(t1, wA.y, bA.y));
            v11 = make_float2(fmaf(t1, wB.x, bB.x), fmaf(t1, wB.y, bB.y));
        } else {
            float bias = (qq == 0) ? 1.0f : 0.0f;
            v00 = make_float2(bias, 0.0f);  v01 = make_float2(0.0f, 0.0f);
            v10 = make_float2(bias, 0.0f);  v11 = make_float2(0.0f, 0.0f);
        }
        uint4 a;
        a.x = pack_h2(v00.x, v00.y);
        a.y = pack_h2(v10.x, v10.y);
        a.z = pack_h2(v01.x, v01.y);
        a.w = pack_h2(v11.x, v11.y);
        #pragma unroll
        for (int nt = 0; nt < 8; ++nt) {
            uint2 b = bbase[(kt * 8 + nt) * 32];
            mma16816(acc[nt], a, b.x, b.y);
        }
    }

    float v0 = 0.0f, v1 = 0.0f;
    #pragma unroll
    for (int nt = 0; nt < 8; ++nt) {
        int col = nt * 8 + qq * 2;
        float w20 = W2[col], w21 = W2[col + 1];
        v0 = fmaf(fmaxf(acc[nt][0], 0.0f), w20, v0);
        v0 = fmaf(fmaxf(acc[nt][1], 0.0f), w21, v0);
        v1 = fmaf(fmaxf(acc[nt][2], 0.0f), w20, v1);
        v1 = fmaf(fmaxf(acc[nt][3], 0.0f), w21, v1);
    }
    v0 += __shfl_xor_sync(0xffffffffu, v0, 1);
    v0 += __shfl_xor_sync(0xffffffffu, v0, 2);
    v1 += __shfl_xor_sync(0xffffffffu, v1, 1);
    v1 += __shfl_xor_sync(0xffffffffu, v1, 2);
    if (qq == 0) {
        float bb = b2[0];
        prob[r0] = sigf(v0 + bb);
        prob[r1] = sigf(v1 + bb);
    }
}

// ---------------------------------------------------------------------------
extern "C" void kernel_launch(void* const* d_in, const int* in_sizes, int n_in,
                              void* d_out, int out_size)
{
    const int*   src_ids    = (const int*)  d_in[0];
    const int*   dst_ids    = (const int*)  d_in[1];
    const int*   etype_ids  = (const int*)  d_in[2];
    const float* t_rel      = (const float*)d_in[3];
    const float* node_cont  = (const float*)d_in[4];
    const int*   ncat_codes = (const int*)  d_in[5];
    const int*   ecat_codes = (const int*)  d_in[6];
    /* d_in[7] = edge_index, unused */
    const float* h_prev     = (const float*)d_in[8];
    const float* c_prev     = (const float*)d_in[9];
    const float* ncat_emb   = (const float*)d_in[10];
    const float* eid_emb    = (const float*)d_in[11];
    const float* ecat_emb   = (const float*)d_in[12];
    const float* time_W     = (const float*)d_in[13];
    const float* time_b     = (const float*)d_in[14];
    const float* Wx         = (const float*)d_in[15];
    const float* Wh         = (const float*)d_in[16];
    const float* b_gate     = (const float*)d_in[17];
    const float* w_c        = (const float*)d_in[18];
    const float* W1         = (const float*)d_in[19];
    const float* b1         = (const float*)d_in[20];
    const float* W2         = (const float*)d_in[21];
    const float* b2         = (const float*)d_in[22];

    float* out   = (float*)d_out;
    float* prob  = out;
    float* h_new = out + B_EDGES;
    float* c_new = out + B_EDGES + (size_t)N_NODES * H;

    prep_all_kernel<<<(KTILES * 32 * 32 * 4 + 255) / 256, 256>>>(Wx, Wh, b_gate, W1, b1);

    build_a_kernel<<<M_TILES, 256>>>(node_cont, ncat_codes, ncat_emb, h_prev);

    gemm_lstm_kernel<<<M_TILES * 8, 256>>>(c_prev, w_c, h_new, c_new);

    edge_mlp_tc_kernel<<<B_EDGES / 64, 128>>>(
        src_ids, dst_ids, etype_ids, t_rel,
        ecat_codes, eid_emb, ecat_emb, time_W, time_b,
        W2, b2, h_new, prob);
}

// round 16
// speedup vs baseline: 1.7314x; 1.7314x over previous
#include <cuda_runtime.h>
#include <cuda_fp16.h>
#include <math.h>
#include <stdint.h>

#define N_NODES 150000
#define N_ETYPES 1000
#define B_EDGES 16384
#define H 128
#define P_IN 336
#define P_HID 64

// Node GEMM: z[150016, 512] = A[150016, 192] @ W[192, 512]  (pure fp16, f32 accum)
// Column permutation (physical fragment col p -> logical gate/h):
//   g = (p&1) | (((p>>3)&1)<<1),  h = ((p>>1)&3) | ((p>>4)<<2)
#define KTILES 12
#define MTILE 128
#define M_TILES 1172           // ceil(150000/128); 150016 padded rows

// Edge GEMM: hid[16384, 64] = comb[16384, 352] @ W1e[352, 64]
#define EKT 22                 // 352/16

// B fragments (node W), uint4 per lane: [sl(12)][npair(32)][lane(32)] uint4
__device__ __align__(16) uint4 g_Wpack4[KTILES * 32 * 32];
// A fragments: [mt(1172)][kt(12)][sub(8)][lane(32)] uint4  (57.6 MB)
__device__ __align__(16) uint4 g_Aext[(size_t)M_TILES * 12 * 8 * 32];
// W1 fragments (edge): [kt(22)][nt(8)][lane(32)] uint2
__device__ __align__(16) uint2 g_W1pack[EKT * 8 * 32];

// ---------------------------------------------------------------------------
__device__ __forceinline__ unsigned short f2h_bits(float f) {
    return __half_as_ushort(__float2half_rn(f));
}
__device__ __forceinline__ uint32_t pack_h2(float a, float b) {
    return (uint32_t)f2h_bits(a) | ((uint32_t)f2h_bits(b) << 16);
}
// single-MUFU nonlinearities (MUFU.TANH): tanh direct; sigmoid via identity
__device__ __forceinline__ float tanh_mufu(float x) {
    float y;
    asm("tanh.approx.f32 %0, %1;" : "=f"(y) : "f"(x));
    return y;
}
__device__ __forceinline__ float sig_mufu(float x) {
    return fmaf(0.5f, tanh_mufu(0.5f * x), 0.5f);
}
// exp-based sigmoid for the edge kernel's final output (1 call/edge, keep precise)
__device__ __forceinline__ float sigf(float x) {
    return __fdividef(1.0f, 1.0f + __expf(-x));
}
__device__ __forceinline__ void mma16816(float* c, const uint4 a, uint32_t bx, uint32_t by) {
    asm volatile("mma.sync.aligned.m16n8k16.row.col.f32.f16.f16.f32 "
        "{%0,%1,%2,%3}, {%4,%5,%6,%7}, {%8,%9}, {%0,%1,%2,%3};"
        : "+f"(c[0]), "+f"(c[1]), "+f"(c[2]), "+f"(c[3])
        : "r"(a.x), "r"(a.y), "r"(a.z), "r"(a.w), "r"(bx), "r"(by));
}

// ---------------------------------------------------------------------------
// Kernel 1: pack node W and edge W1e fragments (merged, one launch).
// ---------------------------------------------------------------------------
__device__ __forceinline__ unsigned short w_bits_gh(
    int k, int g, int h, const float* Wx, const float* Wh, const float* bg)
{
    float w;
    if (k < 128)       w = Wh[(g * 128 + k) * 128 + h];
    else if (k < 178)  w = Wx[(g * 50 + (k - 128)) * 128 + h];
    else if (k == 178) w = bg[g * 128 + h];
    else               w = 0.0f;
    return f2h_bits(w);
}
__device__ __forceinline__ unsigned short w1e_bits(
    int k, int n, const float* W1, const float* b1)
{
    float w;
    if (k < P_IN)       w = W1[k * P_HID + n];
    else if (k == P_IN) w = b1[n];
    else                w = 0.0f;
    return f2h_bits(w);
}

__global__ void prep_all_kernel(const float* __restrict__ Wx,
                                const float* __restrict__ Wh,
                                const float* __restrict__ bg,
                                const float* __restrict__ W1,
                                const float* __restrict__ b1)
{
    int idx = blockIdx.x * blockDim.x + threadIdx.x;
    if (idx < KTILES * 32 * 32 * 4) {
        int r    = idx & 3;
        int lane = (idx >> 2) & 31;
        int np   = (idx >> 7) & 31;
        int sl   = idx >> 12;
        int n8   = np * 2 + (r >> 1);
        int whc  = r & 1;
        int p    = n8 * 8 + (lane >> 2);
        int g    = (p & 1) | (((p >> 3) & 1) << 1);
        int h    = ((p >> 1) & 3) | ((p >> 4) << 2);
        int k0   = sl * 16 + (lane & 3) * 2 + whc * 8;
        unsigned short u0 = w_bits_gh(k0,     g, h, Wx, Wh, bg);
        unsigned short u1 = w_bits_gh(k0 + 1, g, h, Wx, Wh, bg);
        ((uint32_t*)g_Wpack4)[idx] = (uint32_t)u0 | ((uint32_t)u1 << 16);
    }
    if (idx < EKT * 8 * 32 * 2) {
        int r    = idx & 1;
        int lane = (idx >> 1) & 31;
        int nt   = (idx >> 6) & 7;
        int kt   = idx >> 9;
        int n    = nt * 8 + (lane >> 2);
        int k0   = kt * 16 + (lane & 3) * 2 + r * 8;
        unsigned short u0 = w1e_bits(k0,     n, W1, b1);
        unsigned short u1 = w1e_bits(k0 + 1, n, W1, b1);
        ((uint32_t*)g_W1pack)[idx] = (uint32_t)u0 | ((uint32_t)u1 << 16);
    }
}

// ---------------------------------------------------------------------------
// Kernel 2: build A in mma A-fragment order (single fp16 pass). (R10 exact)
// ---------------------------------------------------------------------------
__global__ void __launch_bounds__(256) build_a_kernel(
    const float* __restrict__ node_cont,
    const int*   __restrict__ ncat_codes,
    const float* __restrict__ ncat_emb,
    const float* __restrict__ h_prev)
{
    __shared__ float xs[128][64];

    const int tid  = threadIdx.x;
    const int lane = tid & 31;
    const int w    = tid >> 5;
    const int mt   = blockIdx.x;
    const int n0m  = mt * MTILE;

    for (int it = 0; it < 32; ++it) {
        int e = tid + it * 256;
        int row = e >> 6, kr = e & 63;
        int node = n0m + row;
        float v = 0.0f;
        if (node < N_NODES) {
            if (kr < 2)        v = node_cont[node * 2 + kr];
            else if (kr < 50)  {
                int j = (kr - 2) >> 4, kd = (kr - 2) & 15;
                int code = ncat_codes[j * N_NODES + node];
                v = ncat_emb[(j * 64 + code) * 16 + kd];
            } else if (kr == 50) v = 1.0f;
        }
        xs[row][kr] = v;
    }
    __syncthreads();

    const int gr   = lane >> 2;
    const int kc   = (lane & 3) * 2;
    const int r0   = w * 16 + gr;
    const int r1   = r0 + 8;
    const int nd0  = n0m + r0;
    const int nd1  = n0m + r1;

    #pragma unroll 2
    for (int sl = 0; sl < 12; ++sl) {
        int kg = sl * 16 + kc;
        float2 s00, s01, s10, s11;
        if (kg < 128) {
            s00 = (nd0 < N_NODES) ? *(const float2*)(h_prev + (size_t)nd0 * H + kg)
                                  : make_float2(0.f, 0.f);
            s10 = (nd1 < N_NODES) ? *(const float2*)(h_prev + (size_t)nd1 * H + kg)
                                  : make_float2(0.f, 0.f);
        } else {
            s00 = *(const float2*)&xs[r0][kg - 128];
            s10 = *(const float2*)&xs[r1][kg - 128];
        }
        int kg8 = kg + 8;
        if (kg8 < 128) {
            s01 = (nd0 < N_NODES) ? *(const float2*)(h_prev + (size_t)nd0 * H + kg8)
                                  : make_float2(0.f, 0.f);
            s11 = (nd1 < N_NODES) ? *(const float2*)(h_prev + (size_t)nd1 * H + kg8)
                                  : make_float2(0.f, 0.f);
        } else {
            s01 = *(const float2*)&xs[r0][kg8 - 128];
            s11 = *(const float2*)&xs[r1][kg8 - 128];
        }
        uint4 hi4;
        hi4.x = pack_h2(s00.x, s00.y);
        hi4.y = pack_h2(s10.x, s10.y);
        hi4.z = pack_h2(s01.x, s01.y);
        hi4.w = pack_h2(s11.x, s11.y);
        g_Aext[(((size_t)mt * 12 + sl) * 8 + w) * 32 + lane] = hi4;
    }
}

// ---------------------------------------------------------------------------
// Kernel 3: GEMM + fused LSTM epilogue (R14 exact: f32 accum, MUFU.TANH).
// 256 thr = 8 warps (4m x 2n), warp tile 32x32, 3 CTAs/SM.
// ---------------------------------------------------------------------------
__global__ void __launch_bounds__(256, 3) gemm_lstm_kernel(
    const float* __restrict__ c_prev,
    const float* __restrict__ w_c,
    float* __restrict__ h_new,
    float* __restrict__ c_new)
{
    const int tid  = threadIdx.x;
    const int lane = tid & 31;
    const int wid  = tid >> 5;
    const int wm   = wid & 3;          // 0..3
    const int wn   = wid >> 2;         // 0..1
    const int mt   = blockIdx.x >> 3;
    const int c    = blockIdx.x & 7;
    const int Cw   = c * 2 + wn;       // 32-col warp chunk 0..15

    float acc[2][4][4];
    #pragma unroll
    for (int mtt = 0; mtt < 2; ++mtt)
        #pragma unroll
        for (int nt = 0; nt < 4; ++nt)
            #pragma unroll
            for (int q = 0; q < 4; ++q) acc[mtt][nt][q] = 0.0f;

    const uint4* __restrict__ abase =
        g_Aext + ((size_t)mt * 12 * 8 + wm * 2) * 32 + lane;
    const uint4* __restrict__ bbase =
        g_Wpack4 + (Cw * 2) * 32 + lane;

    #pragma unroll 2
    for (int kt = 0; kt < KTILES; ++kt) {
        uint4 a0 = abase[(size_t)(kt * 8 + 0) * 32];
        uint4 a1 = abase[(size_t)(kt * 8 + 1) * 32];
        uint4 b0 = bbase[(size_t)(kt * 32 + 0) * 32];
        uint4 b1 = bbase[(size_t)(kt * 32 + 1) * 32];
        mma16816(acc[0][0], a0, b0.x, b0.y);
        mma16816(acc[1][0], a1, b0.x, b0.y);
        mma16816(acc[0][1], a0, b0.z, b0.w);
        mma16816(acc[1][1], a1, b0.z, b0.w);
        mma16816(acc[0][2], a0, b1.x, b1.y);
        mma16816(acc[1][2], a1, b1.x, b1.y);
        mma16816(acc[0][3], a0, b1.z, b1.w);
        mma16816(acc[1][3], a1, b1.z, b1.w);
    }

    // ---- fused LSTM epilogue (5 MUFU/cell via tanh.approx).
    const int gr = lane >> 2, qq = lane & 3;
    #pragma unroll
    for (int j = 0; j < 2; ++j) {
        const int h = (Cw * 2 + j) * 4 + qq;
        const float wi = w_c[h];
        const float wf = w_c[128 + h];
        const float wo = w_c[256 + h];
        #pragma unroll
        for (int mtt = 0; mtt < 2; ++mtt) {
            size_t node0 = (size_t)mt * 128 + wm * 32 + mtt * 16 + gr;
            #pragma unroll
            for (int half = 0; half < 2; ++half) {
                size_t node = node0 + half * 8;
                if (node < N_NODES) {
                    int qb = half * 2;
                    float z0 = acc[mtt][2*j][qb],   z1 = acc[mtt][2*j][qb+1];
                    float z2 = acc[mtt][2*j+1][qb], z3 = acc[mtt][2*j+1][qb+1];
                    size_t off = node * H + h;
                    float cv = c_prev[off];
                    float ig = sig_mufu(z0 + wi * cv);
                    float fg = sig_mufu(z1 + wf * cv);
                    float tg = tanh_mufu(z2);
                    float cn = fg * cv + ig * tg;
                    float og = sig_mufu(z3 + wo * cn);
                    c_new[off] = cn;
                    h_new[off] = og * tanh_mufu(cn);
                }
            }
        }
    }
}

// ---------------------------------------------------------------------------
// Kernel 4: Edge MLP via tensor cores (R12/R14 exact: 256-thr blocks, grid 128).
// ---------------------------------------------------------------------------
__global__ void __launch_bounds__(256) edge_mlp_tc_kernel(
    const int*   __restrict__ src_ids, const int* __restrict__ dst_ids,
    const int*   __restrict__ etype_ids, const float* __restrict__ t_rel,
    const int*   __restrict__ ecat_codes, const float* __restrict__ eid_emb,
    const float* __restrict__ ecat_emb, const float* __restrict__ time_W,
    const float* __restrict__ time_b, const float* __restrict__ W2,
    const float* __restrict__ b2, const float* __restrict__ h_new,
    float* __restrict__ prob)
{
    const int lane = threadIdx.x & 31;
    const int w    = threadIdx.x >> 5;
    const int gr   = lane >> 2;
    const int qq   = lane & 3;

    const int r0 = blockIdx.x * 128 + w * 16 + gr;
    const int r1 = r0 + 8;

    const int e0 = etype_ids[r0], e1 = etype_ids[r1];
    const float t0 = t_rel[r0],   t1 = t_rel[r1];
    const float* ps0 = h_new + (size_t)src_ids[r0] * H;
    const float* ps1 = h_new + (size_t)src_ids[r1] * H;
    const float* pd0 = h_new + (size_t)dst_ids[r0] * H;
    const float* pd1 = h_new + (size_t)dst_ids[r1] * H;
    const float* pe0 = eid_emb + e0 * 32;
    const float* pe1 = eid_emb + e1 * 32;
    const float* pc00 = ecat_emb + ecat_codes[e0] * 16;
    const float* pc01 = ecat_emb + (32 + ecat_codes[N_ETYPES + e0]) * 16;
    const float* pc10 = ecat_emb + ecat_codes[e1] * 16;
    const float* pc11 = ecat_emb + (32 + ecat_codes[N_ETYPES + e1]) * 16;

    float acc[8][4];
    #pragma unroll
    for (int nt = 0; nt < 8; ++nt)
        #pragma unroll
        for (int q = 0; q < 4; ++q) acc[nt][q] = 0.0f;

    const uint2* __restrict__ bbase = g_W1pack + lane;
    const int off = qq * 2;

    #pragma unroll
    for (int kt = 0; kt < EKT; ++kt) {
        float2 v00, v01, v10, v11;
        if (kt < 8) {
            int o = kt * 16 + off;
            v00 = *(const float2*)(ps0 + o);     v01 = *(const float2*)(ps0 + o + 8);
            v10 = *(const float2*)(ps1 + o);     v11 = *(const float2*)(ps1 + o + 8);
        } else if (kt < 16) {
            int o = (kt - 8) * 16 + off;
            v00 = *(const float2*)(pd0 + o);     v01 = *(const float2*)(pd0 + o + 8);
            v10 = *(const float2*)(pd1 + o);     v11 = *(const float2*)(pd1 + o + 8);
        } else if (kt < 18) {
            int o = (kt - 16) * 16 + off;
            v00 = *(const float2*)(pe0 + o);     v01 = *(const float2*)(pe0 + o + 8);
            v10 = *(const float2*)(pe1 + o);     v11 = *(const float2*)(pe1 + o + 8);
        } else if (kt == 18) {
            v00 = *(const float2*)(pc00 + off);  v01 = *(const float2*)(pc00 + off + 8);
            v10 = *(const float2*)(pc10 + off);  v11 = *(const float2*)(pc10 + off + 8);
        } else if (kt == 19) {
            v00 = *(const float2*)(pc01 + off);  v01 = *(const float2*)(pc01 + off + 8);
            v10 = *(const float2*)(pc11 + off);  v11 = *(const float2*)(pc11 + off + 8);
        } else if (kt == 20) {
            float2 wA = *(const float2*)(time_W + off);
            float2 wB = *(const float2*)(time_W + off + 8);
            float2 bA = *(const float2*)(time_b + off);
            float2 bB = *(const float2*)(time_b + off + 8);
            v00 = make_float2(fmaf(t0, wA.x, bA.x), fmaf(t0, wA.y, bA.y));
            v01 = make_float2(fmaf(t0, wB.x, bB.x), fmaf(t0, wB.y, bB.y));
            v10 = make_float2(fmaf(t1, wA.x, bA.x), fmaf(t1, wA.y, bA.y));
            v11 = make_float2(fmaf(t1, wB.x, bB.x), fmaf(t1, wB.y, bB.y));
        } else {
            float bias = (qq == 0) ? 1.0f : 0.0f;
            v00 = make_float2(bias, 0.0f);  v01 = make_float2(0.0f, 0.0f);
            v10 = make_float2(bias, 0.0f);  v11 = make_float2(0.0f, 0.0f);
        }
        uint4 a;
        a.x = pack_h2(v00.x, v00.y);
        a.y = pack_h2(v10.x, v10.y);
        a.z = pack_h2(v01.x, v01.y);
        a.w = pack_h2(v11.x, v11.y);
        #pragma unroll
        for (int nt = 0; nt < 8; ++nt) {
            uint2 b = bbase[(kt * 8 + nt) * 32];
            mma16816(acc[nt], a, b.x, b.y);
        }
    }

    float v0 = 0.0f, v1 = 0.0f;
    #pragma unroll
    for (int nt = 0; nt < 8; ++nt) {
        int col = nt * 8 + qq * 2;
        float w20 = W2[col], w21 = W2[col + 1];
        v0 = fmaf(fmaxf(acc[nt][0], 0.0f), w20, v0);
        v0 = fmaf(fmaxf(acc[nt][1], 0.0f), w21, v0);
        v1 = fmaf(fmaxf(acc[nt][2], 0.0f), w20, v1);
        v1 = fmaf(fmaxf(acc[nt][3], 0.0f), w21, v1);
    }
    v0 += __shfl_xor_sync(0xffffffffu, v0, 1);
    v0 += __shfl_xor_sync(0xffffffffu, v0, 2);
    v1 += __shfl_xor_sync(0xffffffffu, v1, 1);
    v1 += __shfl_xor_sync(0xffffffffu, v1, 2);
    if (qq == 0) {
        float bb = b2[0];
        prob[r0] = sigf(v0 + bb);
        prob[r1] = sigf(v1 + bb);
    }
}

// ---------------------------------------------------------------------------
extern "C" void kernel_launch(void* const* d_in, const int* in_sizes, int n_in,
                              void* d_out, int out_size)
{
    const int*   src_ids    = (const int*)  d_in[0];
    const int*   dst_ids    = (const int*)  d_in[1];
    const int*   etype_ids  = (const int*)  d_in[2];
    const float* t_rel      = (const float*)d_in[3];
    const float* node_cont  = (const float*)d_in[4];
    const int*   ncat_codes = (const int*)  d_in[5];
    const int*   ecat_codes = (const int*)  d_in[6];
    /* d_in[7] = edge_index, unused */
    const float* h_prev     = (const float*)d_in[8];
    const float* c_prev     = (const float*)d_in[9];
    const float* ncat_emb   = (const float*)d_in[10];
    const float* eid_emb    = (const float*)d_in[11];
    const float* ecat_emb   = (const float*)d_in[12];
    const float* time_W     = (const float*)d_in[13];
    const float* time_b     = (const float*)d_in[14];
    const float* Wx         = (const float*)d_in[15];
    const float* Wh         = (const float*)d_in[16];
    const float* b_gate     = (const float*)d_in[17];
    const float* w_c        = (const float*)d_in[18];
    const float* W1         = (const float*)d_in[19];
    const float* b1         = (const float*)d_in[20];
    const float* W2         = (const float*)d_in[21];
    const float* b2         = (const float*)d_in[22];

    float* out   = (float*)d_out;
    float* prob  = out;
    float* h_new = out + B_EDGES;
    float* c_new = out + B_EDGES + (size_t)N_NODES * H;

    prep_all_kernel<<<(KTILES * 32 * 32 * 4 + 255) / 256, 256>>>(Wx, Wh, b_gate, W1, b1);

    build_a_kernel<<<M_TILES, 256>>>(node_cont, ncat_codes, ncat_emb, h_prev);

    gemm_lstm_kernel<<<M_TILES * 8, 256>>>(c_prev, w_c, h_new, c_new);

    edge_mlp_tc_kernel<<<B_EDGES / 128, 256>>>(
        src_ids, dst_ids, etype_ids, t_rel,
        ecat_codes, eid_emb, ecat_emb, time_W, time_b,
        W2, b2, h_new, prob);
}

// round 17
// speedup vs baseline: 1.8036x; 1.0417x over previous
#include <cuda_runtime.h>
#include <cuda_fp16.h>
#include <math.h>
#include <stdint.h>

#define N_NODES 150000
#define N_ETYPES 1000
#define B_EDGES 16384
#define H 128
#define P_IN 336
#define P_HID 64

// Node GEMM: z[150016, 512] = A[150016, 192] @ W[192, 512]  (pure fp16, f32 accum)
// Column permutation (physical fragment col p -> logical gate/h):
//   g = (p&1) | (((p>>3)&1)<<1),  h = ((p>>1)&3) | ((p>>4)<<2)
#define KTILES 12
#define MTILE 128
#define M_TILES 1172           // ceil(150000/128); 150016 padded rows

// Edge GEMM: hid[16384, 64] = comb[16384, 352] @ W1e[352, 64]
#define EKT 22                 // 352/16

#define WPACK_U32 (KTILES * 32 * 32 * 4)   // 49152
#define W1PACK_U32 (EKT * 8 * 32 * 2)      // 11264
#define PREP_BLOCKS ((WPACK_U32 + 255) / 256)  // 192 (covers W1PACK too)

// B fragments (node W), uint4 per lane: [sl(12)][npair(32)][lane(32)] uint4
__device__ __align__(16) uint4 g_Wpack4[KTILES * 32 * 32];
// A fragments: [mt(1172)][kt(12)][sub(8)][lane(32)] uint4  (57.6 MB)
__device__ __align__(16) uint4 g_Aext[(size_t)M_TILES * 12 * 8 * 32];
// W1 fragments (edge): [kt(22)][nt(8)][lane(32)] uint2
__device__ __align__(16) uint2 g_W1pack[EKT * 8 * 32];

// ---------------------------------------------------------------------------
__device__ __forceinline__ unsigned short f2h_bits(float f) {
    return __half_as_ushort(__float2half_rn(f));
}
__device__ __forceinline__ uint32_t pack_h2(float a, float b) {
    return (uint32_t)f2h_bits(a) | ((uint32_t)f2h_bits(b) << 16);
}
// single-MUFU nonlinearities (MUFU.TANH)
__device__ __forceinline__ float tanh_mufu(float x) {
    float y;
    asm("tanh.approx.f32 %0, %1;" : "=f"(y) : "f"(x));
    return y;
}
__device__ __forceinline__ float sig_mufu(float x) {
    return fmaf(0.5f, tanh_mufu(0.5f * x), 0.5f);
}
__device__ __forceinline__ float sigf(float x) {
    return __fdividef(1.0f, 1.0f + __expf(-x));
}
__device__ __forceinline__ void mma16816(float* c, const uint4 a, uint32_t bx, uint32_t by) {
    asm volatile("mma.sync.aligned.m16n8k16.row.col.f32.f16.f16.f32 "
        "{%0,%1,%2,%3}, {%4,%5,%6,%7}, {%8,%9}, {%0,%1,%2,%3};"
        : "+f"(c[0]), "+f"(c[1]), "+f"(c[2]), "+f"(c[3])
        : "r"(a.x), "r"(a.y), "r"(a.z), "r"(a.w), "r"(bx), "r"(by));
}

// ---------------------------------------------------------------------------
// Weight-element helpers (fp16 bits).
// ---------------------------------------------------------------------------
__device__ __forceinline__ unsigned short w_bits_gh(
    int k, int g, int h, const float* Wx, const float* Wh, const float* bg)
{
    float w;
    if (k < 128)       w = Wh[(g * 128 + k) * 128 + h];
    else if (k < 178)  w = Wx[(g * 50 + (k - 128)) * 128 + h];
    else if (k == 178) w = bg[g * 128 + h];
    else               w = 0.0f;
    return f2h_bits(w);
}
__device__ __forceinline__ unsigned short w1e_bits(
    int k, int n, const float* W1, const float* b1)
{
    float w;
    if (k < P_IN)       w = W1[k * P_HID + n];
    else if (k == P_IN) w = b1[n];
    else                w = 0.0f;
    return f2h_bits(w);
}

// ---------------------------------------------------------------------------
// Kernel 1: build A in mma A-fragment order + weight prep (fused).
// Blocks [0, M_TILES): A build. Blocks [M_TILES, M_TILES+PREP_BLOCKS): prep.
// ---------------------------------------------------------------------------
__global__ void __launch_bounds__(256) build_a_prep_kernel(
    const float* __restrict__ node_cont,
    const int*   __restrict__ ncat_codes,
    const float* __restrict__ ncat_emb,
    const float* __restrict__ h_prev,
    const float* __restrict__ Wx,
    const float* __restrict__ Wh,
    const float* __restrict__ bg,
    const float* __restrict__ W1,
    const float* __restrict__ b1)
{
    const int tid  = threadIdx.x;

    if (blockIdx.x >= M_TILES) {
        // ---- weight prep path
        int idx = (blockIdx.x - M_TILES) * 256 + tid;
        if (idx < WPACK_U32) {
            int r    = idx & 3;
            int lane = (idx >> 2) & 31;
            int np   = (idx >> 7) & 31;
            int sl   = idx >> 12;
            int n8   = np * 2 + (r >> 1);
            int whc  = r & 1;
            int p    = n8 * 8 + (lane >> 2);
            int g    = (p & 1) | (((p >> 3) & 1) << 1);
            int h    = ((p >> 1) & 3) | ((p >> 4) << 2);
            int k0   = sl * 16 + (lane & 3) * 2 + whc * 8;
            unsigned short u0 = w_bits_gh(k0,     g, h, Wx, Wh, bg);
            unsigned short u1 = w_bits_gh(k0 + 1, g, h, Wx, Wh, bg);
            ((uint32_t*)g_Wpack4)[idx] = (uint32_t)u0 | ((uint32_t)u1 << 16);
        }
        if (idx < W1PACK_U32) {
            int r    = idx & 1;
            int lane = (idx >> 1) & 31;
            int nt   = (idx >> 6) & 7;
            int kt   = idx >> 9;
            int n    = nt * 8 + (lane >> 2);
            int k0   = kt * 16 + (lane & 3) * 2 + r * 8;
            unsigned short u0 = w1e_bits(k0,     n, W1, b1);
            unsigned short u1 = w1e_bits(k0 + 1, n, W1, b1);
            ((uint32_t*)g_W1pack)[idx] = (uint32_t)u0 | ((uint32_t)u1 << 16);
        }
        return;
    }

    // ---- A build path (R10 exact)
    __shared__ float xs[128][64];

    const int lane = tid & 31;
    const int w    = tid >> 5;
    const int mt   = blockIdx.x;
    const int n0m  = mt * MTILE;

    for (int it = 0; it < 32; ++it) {
        int e = tid + it * 256;
        int row = e >> 6, kr = e & 63;
        int node = n0m + row;
        float v = 0.0f;
        if (node < N_NODES) {
            if (kr < 2)        v = node_cont[node * 2 + kr];
            else if (kr < 50)  {
                int j = (kr - 2) >> 4, kd = (kr - 2) & 15;
                int code = ncat_codes[j * N_NODES + node];
                v = ncat_emb[(j * 64 + code) * 16 + kd];
            } else if (kr == 50) v = 1.0f;
        }
        xs[row][kr] = v;
    }
    __syncthreads();

    const int gr   = lane >> 2;
    const int kc   = (lane & 3) * 2;
    const int r0   = w * 16 + gr;
    const int r1   = r0 + 8;
    const int nd0  = n0m + r0;
    const int nd1  = n0m + r1;

    #pragma unroll 2
    for (int sl = 0; sl < 12; ++sl) {
        int kg = sl * 16 + kc;
        float2 s00, s01, s10, s11;
        if (kg < 128) {
            s00 = (nd0 < N_NODES) ? *(const float2*)(h_prev + (size_t)nd0 * H + kg)
                                  : make_float2(0.f, 0.f);
            s10 = (nd1 < N_NODES) ? *(const float2*)(h_prev + (size_t)nd1 * H + kg)
                                  : make_float2(0.f, 0.f);
        } else {
            s00 = *(const float2*)&xs[r0][kg - 128];
            s10 = *(const float2*)&xs[r1][kg - 128];
        }
        int kg8 = kg + 8;
        if (kg8 < 128) {
            s01 = (nd0 < N_NODES) ? *(const float2*)(h_prev + (size_t)nd0 * H + kg8)
                                  : make_float2(0.f, 0.f);
            s11 = (nd1 < N_NODES) ? *(const float2*)(h_prev + (size_t)nd1 * H + kg8)
                                  : make_float2(0.f, 0.f);
        } else {
            s01 = *(const float2*)&xs[r0][kg8 - 128];
            s11 = *(const float2*)&xs[r1][kg8 - 128];
        }
        uint4 hi4;
        hi4.x = pack_h2(s00.x, s00.y);
        hi4.y = pack_h2(s10.x, s10.y);
        hi4.z = pack_h2(s01.x, s01.y);
        hi4.w = pack_h2(s11.x, s11.y);
        g_Aext[(((size_t)mt * 12 + sl) * 8 + w) * 32 + lane] = hi4;
    }
}

// ---------------------------------------------------------------------------
// Kernel 2: GEMM + fused LSTM epilogue (R14 exact: f32 accum, MUFU.TANH).
// 256 thr = 8 warps (4m x 2n), warp tile 32x32, 3 CTAs/SM.
// ---------------------------------------------------------------------------
__global__ void __launch_bounds__(256, 3) gemm_lstm_kernel(
    const float* __restrict__ c_prev,
    const float* __restrict__ w_c,
    float* __restrict__ h_new,
    float* __restrict__ c_new)
{
    const int tid  = threadIdx.x;
    const int lane = tid & 31;
    const int wid  = tid >> 5;
    const int wm   = wid & 3;          // 0..3
    const int wn   = wid >> 2;         // 0..1
    const int mt   = blockIdx.x >> 3;
    const int c    = blockIdx.x & 7;
    const int Cw   = c * 2 + wn;       // 32-col warp chunk 0..15

    float acc[2][4][4];
    #pragma unroll
    for (int mtt = 0; mtt < 2; ++mtt)
        #pragma unroll
        for (int nt = 0; nt < 4; ++nt)
            #pragma unroll
            for (int q = 0; q < 4; ++q) acc[mtt][nt][q] = 0.0f;

    const uint4* __restrict__ abase =
        g_Aext + ((size_t)mt * 12 * 8 + wm * 2) * 32 + lane;
    const uint4* __restrict__ bbase =
        g_Wpack4 + (Cw * 2) * 32 + lane;

    #pragma unroll 2
    for (int kt = 0; kt < KTILES; ++kt) {
        uint4 a0 = abase[(size_t)(kt * 8 + 0) * 32];
        uint4 a1 = abase[(size_t)(kt * 8 + 1) * 32];
        uint4 b0 = bbase[(size_t)(kt * 32 + 0) * 32];
        uint4 b1 = bbase[(size_t)(kt * 32 + 1) * 32];
        mma16816(acc[0][0], a0, b0.x, b0.y);
        mma16816(acc[1][0], a1, b0.x, b0.y);
        mma16816(acc[0][1], a0, b0.z, b0.w);
        mma16816(acc[1][1], a1, b0.z, b0.w);
        mma16816(acc[0][2], a0, b1.x, b1.y);
        mma16816(acc[1][2], a1, b1.x, b1.y);
        mma16816(acc[0][3], a0, b1.z, b1.w);
        mma16816(acc[1][3], a1, b1.z, b1.w);
    }

    // ---- fused LSTM epilogue (5 MUFU/cell via tanh.approx).
    const int gr = lane >> 2, qq = lane & 3;
    #pragma unroll
    for (int j = 0; j < 2; ++j) {
        const int h = (Cw * 2 + j) * 4 + qq;
        const float wi = w_c[h];
        const float wf = w_c[128 + h];
        const float wo = w_c[256 + h];
        #pragma unroll
        for (int mtt = 0; mtt < 2; ++mtt) {
            size_t node0 = (size_t)mt * 128 + wm * 32 + mtt * 16 + gr;
            #pragma unroll
            for (int half = 0; half < 2; ++half) {
                size_t node = node0 + half * 8;
                if (node < N_NODES) {
                    int qb = half * 2;
                    float z0 = acc[mtt][2*j][qb],   z1 = acc[mtt][2*j][qb+1];
                    float z2 = acc[mtt][2*j+1][qb], z3 = acc[mtt][2*j+1][qb+1];
                    size_t off = node * H + h;
                    float cv = c_prev[off];
                    float ig = sig_mufu(z0 + wi * cv);
                    float fg = sig_mufu(z1 + wf * cv);
                    float tg = tanh_mufu(z2);
                    float cn = fg * cv + ig * tg;
                    float og = sig_mufu(z3 + wo * cn);
                    c_new[off] = cn;
                    h_new[off] = og * tanh_mufu(cn);
                }
            }
        }
    }
}

// ---------------------------------------------------------------------------
// Kernel 3: Edge MLP via tensor cores, N split across warp pairs.
// 256 thr = 8 warps = 4 edge-groups (16 edges) x 2 col-halves (32 cols).
// grid = B_EDGES/64 = 256. Col-half partials combined through smem.
// ---------------------------------------------------------------------------
__global__ void __launch_bounds__(256) edge_mlp_tc_kernel(
    const int*   __restrict__ src_ids, const int* __restrict__ dst_ids,
    const int*   __restrict__ etype_ids, const float* __restrict__ t_rel,
    const int*   __restrict__ ecat_codes, const float* __restrict__ eid_emb,
    const float* __restrict__ ecat_emb, const float* __restrict__ time_W,
    const float* __restrict__ time_b, const float* __restrict__ W2,
    const float* __restrict__ b2, const float* __restrict__ h_new,
    float* __restrict__ prob)
{
    __shared__ float part[4][2][2][8];   // [eg][wn][v0/v1][gr]

    const int lane = threadIdx.x & 31;
    const int w    = threadIdx.x >> 5;   // 0..7
    const int eg   = w >> 1;             // edge group 0..3
    const int wn   = w & 1;              // col half 0..1
    const int gr   = lane >> 2;
    const int qq   = lane & 3;

    const int r0 = blockIdx.x * 64 + eg * 16 + gr;
    const int r1 = r0 + 8;

    const int e0 = etype_ids[r0], e1 = etype_ids[r1];
    const float t0 = t_rel[r0],   t1 = t_rel[r1];
    const float* ps0 = h_new + (size_t)src_ids[r0] * H;
    const float* ps1 = h_new + (size_t)src_ids[r1] * H;
    const float* pd0 = h_new + (size_t)dst_ids[r0] * H;
    const float* pd1 = h_new + (size_t)dst_ids[r1] * H;
    const float* pe0 = eid_emb + e0 * 32;
    const float* pe1 = eid_emb + e1 * 32;
    const float* pc00 = ecat_emb + ecat_codes[e0] * 16;
    const float* pc01 = ecat_emb + (32 + ecat_codes[N_ETYPES + e0]) * 16;
    const float* pc10 = ecat_emb + ecat_codes[e1] * 16;
    const float* pc11 = ecat_emb + (32 + ecat_codes[N_ETYPES + e1]) * 16;

    float acc[4][4];
    #pragma unroll
    for (int nt = 0; nt < 4; ++nt)
        #pragma unroll
        for (int q = 0; q < 4; ++q) acc[nt][q] = 0.0f;

    const uint2* __restrict__ bbase = g_W1pack + (wn * 4) * 32 + lane;
    const int off = qq * 2;

    #pragma unroll
    for (int kt = 0; kt < EKT; ++kt) {
        float2 v00, v01, v10, v11;
        if (kt < 8) {
            int o = kt * 16 + off;
            v00 = *(const float2*)(ps0 + o);     v01 = *(const float2*)(ps0 + o + 8);
            v10 = *(const float2*)(ps1 + o);     v11 = *(const float2*)(ps1 + o + 8);
        } else if (kt < 16) {
            int o = (kt - 8) * 16 + off;
            v00 = *(const float2*)(pd0 + o);     v01 = *(const float2*)(pd0 + o + 8);
            v10 = *(const float2*)(pd1 + o);     v11 = *(const float2*)(pd1 + o + 8);
        } else if (kt < 18) {
            int o = (kt - 16) * 16 + off;
            v00 = *(const float2*)(pe0 + o);     v01 = *(const float2*)(pe0 + o + 8);
            v10 = *(const float2*)(pe1 + o);     v11 = *(const float2*)(pe1 + o + 8);
        } else if (kt == 18) {
            v00 = *(const float2*)(pc00 + off);  v01 = *(const float2*)(pc00 + off + 8);
            v10 = *(const float2*)(pc10 + off);  v11 = *(const float2*)(pc10 + off + 8);
        } else if (kt == 19) {
            v00 = *(const float2*)(pc01 + off);  v01 = *(const float2*)(pc01 + off + 8);
            v10 = *(const float2*)(pc11 + off);  v11 = *(const float2*)(pc11 + off + 8);
        } else if (kt == 20) {
            float2 wA = *(const float2*)(time_W + off);
            float2 wB = *(const float2*)(time_W + off + 8);
            float2 bA = *(const float2*)(time_b + off);
            float2 bB = *(const float2*)(time_b + off + 8);
            v00 = make_float2(fmaf(t0, wA.x, bA.x), fmaf(t0, wA.y, bA.y));
            v01 = make_float2(fmaf(t0, wB.x, bB.x), fmaf(t0, wB.y, bB.y));
            v10 = make_float2(fmaf(t1, wA.x, bA.x), fmaf(t1, wA.y, bA.y));
            v11 = make_float2(fmaf(t1, wB.x, bB.x), fmaf(t1, wB.y, bB.y));
        } else {
            float bias = (qq == 0) ? 1.0f : 0.0f;
            v00 = make_float2(bias, 0.0f);  v01 = make_float2(0.0f, 0.0f);
            v10 = make_float2(bias, 0.0f);  v11 = make_float2(0.0f, 0.0f);
        }
        uint4 a;
        a.x = pack_h2(v00.x, v00.y);
        a.y = pack_h2(v10.x, v10.y);
        a.z = pack_h2(v01.x, v01.y);
        a.w = pack_h2(v11.x, v11.y);
        #pragma unroll
        for (int nt = 0; nt < 4; ++nt) {
            uint2 b = bbase[(kt * 8 + nt) * 32];
            mma16816(acc[nt], a, b.x, b.y);
        }
    }

    // partial W2 reduction over this warp's 32 cols
    float v0 = 0.0f, v1 = 0.0f;
    #pragma unroll
    for (int nt = 0; nt < 4; ++nt) {
        int col = (wn * 4 + nt) * 8 + qq * 2;
        float w20 = W2[col], w21 = W2[col + 1];
        v0 = fmaf(fmaxf(acc[nt][0], 0.0f), w20, v0);
        v0 = fmaf(fmaxf(acc[nt][1], 0.0f), w21, v0);
        v1 = fmaf(fmaxf(acc[nt][2], 0.0f), w20, v1);
        v1 = fmaf(fmaxf(acc[nt][3], 0.0f), w21, v1);
    }
    v0 += __shfl_xor_sync(0xffffffffu, v0, 1);
    v0 += __shfl_xor_sync(0xffffffffu, v0, 2);
    v1 += __shfl_xor_sync(0xffffffffu, v1, 1);
    v1 += __shfl_xor_sync(0xffffffffu, v1, 2);
    if (qq == 0) {
        part[eg][wn][0][gr] = v0;
        part[eg][wn][1][gr] = v1;
    }
    __syncthreads();
    if (wn == 0 && qq == 0) {
        float bb = b2[0];
        prob[r0] = sigf(part[eg][0][0][gr] + part[eg][1][0][gr] + bb);
        prob[r1] = sigf(part[eg][0][1][gr] + part[eg][1][1][gr] + bb);
    }
}

// ---------------------------------------------------------------------------
extern "C" void kernel_launch(void* const* d_in, const int* in_sizes, int n_in,
                              void* d_out, int out_size)
{
    const int*   src_ids    = (const int*)  d_in[0];
    const int*   dst_ids    = (const int*)  d_in[1];
    const int*   etype_ids  = (const int*)  d_in[2];
    const float* t_rel      = (const float*)d_in[3];
    const float* node_cont  = (const float*)d_in[4];
    const int*   ncat_codes = (const int*)  d_in[5];
    const int*   ecat_codes = (const int*)  d_in[6];
    /* d_in[7] = edge_index, unused */
    const float* h_prev     = (const float*)d_in[8];
    const float* c_prev     = (const float*)d_in[9];
    const float* ncat_emb   = (const float*)d_in[10];
    const float* eid_emb    = (const float*)d_in[11];
    const float* ecat_emb   = (const float*)d_in[12];
    const float* time_W     = (const float*)d_in[13];
    const float* time_b     = (const float*)d_in[14];
    const float* Wx         = (const float*)d_in[15];
    const float* Wh         = (const float*)d_in[16];
    const float* b_gate     = (const float*)d_in[17];
    const float* w_c        = (const float*)d_in[18];
    const float* W1         = (const float*)d_in[19];
    const float* b1         = (const float*)d_in[20];
    const float* W2         = (const float*)d_in[21];
    const float* b2         = (const float*)d_in[22];

    float* out   = (float*)d_out;
    float* prob  = out;
    float* h_new = out + B_EDGES;
    float* c_new = out + B_EDGES + (size_t)N_NODES * H;

    build_a_prep_kernel<<<M_TILES + PREP_BLOCKS, 256>>>(
        node_cont, ncat_codes, ncat_emb, h_prev, Wx, Wh, b_gate, W1, b1);

    gemm_lstm_kernel<<<M_TILES * 8, 256>>>(c_prev, w_c, h_new, c_new);

    edge_mlp_tc_kernel<<<B_EDGES / 64, 256>>>(
        src_ids, dst_ids, etype_ids, t_rel,
        ecat_codes, eid_emb, ecat_emb, time_W, time_b,
        W2, b2, h_new, prob);
}